// round 16
// baseline (speedup 1.0000x reference)
#include <cuda_runtime.h>
#include <cuda_bf16.h>
#include <cstdint>

#define N_NODES 100000
#define N_EDGES 1600000
#define D 128
#define DOUT 16
#define CAP 128          // per-node bucket capacity (in-degree ~Poisson(16))

#define BM 128
#define GT 256
#define GEMM_BLOCKS ((N_NODES + BM - 1) / BM)
#define ZERO_BLKS ((N_NODES + 1023) / 1024)   // 98

// ---------------- scratch (static device globals) ---------------------------
__device__ float g_pq[(size_t)N_NODES * 32];   // p (cols 0-15) and q (cols 16-31)
__device__ int   g_cnt[N_NODES];
__device__ int   g_csr[(size_t)N_NODES * CAP]; // bucketed adjacency
__device__ __nv_bfloat16 g_ah[(size_t)N_NODES * D];  // agg hi
__device__ __nv_bfloat16 g_al[(size_t)N_NODES * D];  // agg lo
__device__ __nv_bfloat16 g_xh[(size_t)N_NODES * D];  // x hi
__device__ __nv_bfloat16 g_xl[(size_t)N_NODES * D];  // x lo
__device__ __nv_bfloat16 g_hh[(size_t)N_NODES * D];  // h hi
__device__ __nv_bfloat16 g_hl[(size_t)N_NODES * D];  // h lo
__device__ __nv_bfloat16 g_wh[2 * D * D];      // W1l, W1r hi parts
__device__ __nv_bfloat16 g_wl[2 * D * D];      // W1l, W1r lo parts
__device__ __nv_bfloat16 g_wsh[32 * D];        // stacked [Wcl; Wcr] hi
__device__ __nv_bfloat16 g_wsl[32 * D];        // stacked [Wcl; Wcr] lo
__device__ float g_bco[DOUT];                  // Wc@b2l + bc

// ---------------- helpers ---------------------------------------------------
__device__ __forceinline__ uint32_t packbf(float a, float b) {
    uint16_t ha = __bfloat16_as_ushort(__float2bfloat16_rn(a));
    uint16_t hb = __bfloat16_as_ushort(__float2bfloat16_rn(b));
    return (uint32_t)ha | ((uint32_t)hb << 16);
}
__device__ __forceinline__ float residf(float f) {
    return f - __bfloat162float(__float2bfloat16_rn(f));
}

#define LDSM4(r0, r1, r2, r3, addr)                                            \
    asm volatile("ldmatrix.sync.aligned.m8n8.x4.shared.b16 {%0,%1,%2,%3}, [%4];" \
                 : "=r"(r0), "=r"(r1), "=r"(r2), "=r"(r3) : "r"(addr))

#define MMA16816(cc, a, b0, b1)                                                \
    asm volatile("mma.sync.aligned.m16n8k16.row.col.f32.bf16.bf16.f32 "        \
                 "{%0,%1,%2,%3}, {%4,%5,%6,%7}, {%8,%9}, {%0,%1,%2,%3};"       \
                 : "+f"(cc[0]), "+f"(cc[1]), "+f"(cc[2]), "+f"(cc[3])          \
                 : "r"(a[0]), "r"(a[1]), "r"(a[2]), "r"(a[3]), "r"(b0), "r"(b1))

#define CP_ASYNC16(smem, gmem)                                                 \
    asm volatile("cp.async.ca.shared.global [%0], [%1], 16;"                    \
                 :: "r"(smem), "l"(gmem))
#define CP_COMMIT() asm volatile("cp.async.commit_group;" ::: "memory")
#define CP_WAIT1()  asm volatile("cp.async.wait_group 1;" ::: "memory")
#define CP_WAIT0()  asm volatile("cp.async.wait_group 0;" ::: "memory")

// ---------------- fused prep: zero cnt + weight split + composed weights ----
__global__ void k_prep(const float* __restrict__ W1l, const float* __restrict__ W1r,
                       const float* __restrict__ Wc, const float* __restrict__ W2l,
                       const float* __restrict__ W2r, const float* __restrict__ b2l,
                       const float* __restrict__ bc) {
    int b = blockIdx.x;
    if (b < ZERO_BLKS) {
        int i = b * 1024 + threadIdx.x;
        if (i < N_NODES) g_cnt[i] = 0;
    } else if (b < ZERO_BLKS + 32) {
        int i = (b - ZERO_BLKS) * 1024 + threadIdx.x;
        const float* srcs[2] = {W1l, W1r};
        float v = srcs[i >> 14][i & 16383];
        __nv_bfloat16 h = __float2bfloat16_rn(v);
        g_wh[i] = h;
        g_wl[i] = __float2bfloat16_rn(v - __bfloat162float(h));
    } else {
        int idx = (b - ZERO_BLKS - 32) * 1024 + threadIdx.x;
        int which = idx >> 11;
        int o = (idx >> 7) & 15;
        int k = idx & 127;
        const float* W2 = which ? W2r : W2l;
        float s = 0.f;
#pragma unroll 8
        for (int j = 0; j < D; j++)
            s += Wc[o * D + j] * W2[j * D + k];
        int row = which * 16 + o;
        __nv_bfloat16 hi = __float2bfloat16_rn(s);
        g_wsh[row * D + k] = hi;
        g_wsl[row * D + k] = __float2bfloat16_rn(s - __bfloat162float(hi));
        if (which == 0 && k == 0) {
            float bb = bc[o];
            for (int j = 0; j < D; j++) bb += Wc[o * D + j] * b2l[j];
            g_bco[o] = bb;
        }
    }
}

// ---------------- x -> bf16 hi/lo planes ------------------------------------
__global__ void k_convx(const float* __restrict__ x) {
    size_t i = (size_t)blockIdx.x * blockDim.x + threadIdx.x;  // per 4 elems
    float4 v = ((const float4*)x)[i];
    uint2 h, l;
    h.x = packbf(v.x, v.y);
    h.y = packbf(v.z, v.w);
    l.x = packbf(residf(v.x), residf(v.y));
    l.y = packbf(residf(v.z), residf(v.w));
    ((uint2*)g_xh)[i] = h;
    ((uint2*)g_xl)[i] = l;
}

// ---------------- bucket scatter ---------------------------------------------
__global__ void k_scatter(const int* __restrict__ src, const int* __restrict__ dst) {
    for (int e = blockIdx.x * blockDim.x + threadIdx.x; e < N_EDGES;
         e += gridDim.x * blockDim.x) {
        int d = dst[e];
        int p = atomicAdd(&g_cnt[d], 1);
        if (p < CAP) g_csr[(size_t)d * CAP + p] = src[e];
    }
}

// ---------------- mean aggregation: warp per node; writes bf16 hi/lo --------
__global__ void k_aggregate(const float* __restrict__ feat) {
    int warp = (blockIdx.x * blockDim.x + threadIdx.x) >> 5;
    int lane = threadIdx.x & 31;
    if (warp >= N_NODES) return;
    int deg = min(g_cnt[warp], CAP);
    const int* adj = g_csr + (size_t)warp * CAP;
    float4 acc = make_float4(0.f, 0.f, 0.f, 0.f);
    const float4* f4 = (const float4*)feat;
    for (int i = 0; i < deg; i++) {
        int s = adj[i];
        float4 v = f4[(size_t)s * 32 + lane];
        acc.x += v.x; acc.y += v.y; acc.z += v.z; acc.w += v.w;
    }
    float inv = 1.0f / (float)max(deg, 1);
    acc.x *= inv; acc.y *= inv; acc.z *= inv; acc.w *= inv;
    uint2 h, l;
    h.x = packbf(acc.x, acc.y);
    h.y = packbf(acc.z, acc.w);
    l.x = packbf(residf(acc.x), residf(acc.y));
    l.y = packbf(residf(acc.z), residf(acc.w));
    ((uint2*)g_ah)[(size_t)warp * 32 + lane] = h;
    ((uint2*)g_al)[(size_t)warp * 32 + lane] = l;
}

// ---------------- tensor-core dual GEMM (layer 1), cp.async pipelined -------
// h = relu(agg@W1l^T + x@W1r^T + bias), inputs pre-split bf16 hi/lo.
__global__ __launch_bounds__(GT, 2)
void k_gemm(const float* __restrict__ bias)
{
    __shared__ __align__(16) __nv_bfloat16 sAh[2][BM * 24];
    __shared__ __align__(16) __nv_bfloat16 sAl[2][BM * 24];
    __shared__ __align__(16) __nv_bfloat16 sBh[2][BM * 24];
    __shared__ __align__(16) __nv_bfloat16 sBl[2][BM * 24];
    __shared__ float sbias[D];

    int tid  = threadIdx.x;
    int lane = tid & 31;
    int warp = tid >> 5;
    int warp_m = warp & 3;
    int warp_n = warp >> 2;
    int rowBase = blockIdx.x * BM;

    if (tid < D) sbias[tid] = bias[tid];

    int lrow  = tid >> 1;        // 0..127
    int lhalf = tid & 1;         // 16B half of 16-wide k chunk
    int grow  = min(rowBase + lrow, N_NODES - 1);   // clamp (values unused OOB)

    int ldrow = lane & 15;
    int ldoff = (lane >> 4) * 16;
    uint32_t aoff = (uint32_t)((warp_m * 32 + ldrow) * 48 + ldoff);
    uint32_t boff = (uint32_t)((warp_n * 64 + ldrow) * 48 + ldoff);
    uint32_t sAh_b[2] = {(uint32_t)__cvta_generic_to_shared(sAh[0]),
                         (uint32_t)__cvta_generic_to_shared(sAh[1])};
    uint32_t sAl_b[2] = {(uint32_t)__cvta_generic_to_shared(sAl[0]),
                         (uint32_t)__cvta_generic_to_shared(sAl[1])};
    uint32_t sBh_b[2] = {(uint32_t)__cvta_generic_to_shared(sBh[0]),
                         (uint32_t)__cvta_generic_to_shared(sBh[1])};
    uint32_t sBl_b[2] = {(uint32_t)__cvta_generic_to_shared(sBl[0]),
                         (uint32_t)__cvta_generic_to_shared(sBl[1])};
    uint32_t soff = (uint32_t)(lrow * 48 + lhalf * 16);

    float c[2][8][4];
#pragma unroll
    for (int mt = 0; mt < 2; mt++)
#pragma unroll
        for (int nc = 0; nc < 8; nc++)
#pragma unroll
            for (int r = 0; r < 4; r++) c[mt][nc][r] = 0.f;

    auto load_tile = [&](int t, int buf) {
        int ph = t >> 3;
        int kb = (t & 7) << 4;
        const __nv_bfloat16* Ah = (ph ? g_xh : g_ah) + (size_t)grow * D + kb + lhalf * 8;
        const __nv_bfloat16* Al = (ph ? g_xl : g_al) + (size_t)grow * D + kb + lhalf * 8;
        const __nv_bfloat16* Wh = g_wh + (size_t)ph * D * D + (size_t)lrow * D + kb + lhalf * 8;
        const __nv_bfloat16* Wl = g_wl + (size_t)ph * D * D + (size_t)lrow * D + kb + lhalf * 8;
        CP_ASYNC16(sAh_b[buf] + soff, Ah);
        CP_ASYNC16(sAl_b[buf] + soff, Al);
        CP_ASYNC16(sBh_b[buf] + soff, Wh);
        CP_ASYNC16(sBl_b[buf] + soff, Wl);
    };

    load_tile(0, 0);
    CP_COMMIT();

#pragma unroll 1
    for (int t = 0; t < 16; t++) {
        int cur = t & 1;
        if (t < 15) {
            load_tile(t + 1, cur ^ 1);
            CP_COMMIT();
            CP_WAIT1();
        } else {
            CP_WAIT0();
        }
        __syncthreads();

        uint32_t ah[2][4], al[2][4];
        LDSM4(ah[0][0], ah[0][1], ah[0][2], ah[0][3], sAh_b[cur] + aoff);
        LDSM4(ah[1][0], ah[1][1], ah[1][2], ah[1][3], sAh_b[cur] + aoff + 16 * 48);
        LDSM4(al[0][0], al[0][1], al[0][2], al[0][3], sAl_b[cur] + aoff);
        LDSM4(al[1][0], al[1][1], al[1][2], al[1][3], sAl_b[cur] + aoff + 16 * 48);

#pragma unroll
        for (int ng = 0; ng < 4; ng++) {
            uint32_t bh[4], bl[4];
            LDSM4(bh[0], bh[1], bh[2], bh[3], sBh_b[cur] + boff + ng * 16 * 48);
            LDSM4(bl[0], bl[1], bl[2], bl[3], sBl_b[cur] + boff + ng * 16 * 48);
#pragma unroll
            for (int mt = 0; mt < 2; mt++) {
#pragma unroll
                for (int sub = 0; sub < 2; sub++) {
                    float* cc = c[mt][ng * 2 + sub];
                    MMA16816(cc, ah[mt], bh[sub], bh[sub + 2]);
                    MMA16816(cc, ah[mt], bl[sub], bl[sub + 2]);
                    MMA16816(cc, al[mt], bh[sub], bh[sub + 2]);
                }
            }
        }
        __syncthreads();
    }

    // epilogue: bias + relu, write h as bf16 hi/lo
    int g = lane >> 2;
    int q = (lane & 3) * 2;
#pragma unroll
    for (int mt = 0; mt < 2; mt++) {
        int r0 = rowBase + warp_m * 32 + mt * 16 + g;
#pragma unroll
        for (int nc = 0; nc < 8; nc++) {
            int col = warp_n * 64 + nc * 8 + q;
            float b0 = sbias[col], b1 = sbias[col + 1];
            float* cc = c[mt][nc];
            float o0 = fmaxf(cc[0] + b0, 0.f);
            float o1 = fmaxf(cc[1] + b1, 0.f);
            float o2 = fmaxf(cc[2] + b0, 0.f);
            float o3 = fmaxf(cc[3] + b1, 0.f);
            if (r0 < N_NODES) {
                *(uint32_t*)(g_hh + (size_t)r0 * D + col) = packbf(o0, o1);
                *(uint32_t*)(g_hl + (size_t)r0 * D + col) =
                    packbf(residf(o0), residf(o1));
            }
            if (r0 + 8 < N_NODES) {
                *(uint32_t*)(g_hh + (size_t)(r0 + 8) * D + col) = packbf(o2, o3);
                *(uint32_t*)(g_hl + (size_t)(r0 + 8) * D + col) =
                    packbf(residf(o2), residf(o3));
            }
        }
    }
}

// ---------------- layer-2 composed GEMM: pq = h @ [Wcl;Wcr]^T (N=32) --------
__global__ __launch_bounds__(GT, 2)
void k_gemm16(float* __restrict__ pq)
{
    __shared__ __align__(16) __nv_bfloat16 sAh[BM * 24];
    __shared__ __align__(16) __nv_bfloat16 sAl[BM * 24];
    __shared__ __align__(16) __nv_bfloat16 sBh[32 * 24];
    __shared__ __align__(16) __nv_bfloat16 sBl[32 * 24];

    int tid  = threadIdx.x;
    int lane = tid & 31;
    int warp = tid >> 5;
    int rowBase = blockIdx.x * BM;

    int lrow  = tid >> 1;
    int lhalf = tid & 1;
    int grow  = min(rowBase + lrow, N_NODES - 1);

    int ldrow = lane & 15;
    int ldoff = (lane >> 4) * 16;
    uint32_t aoff = (uint32_t)((warp * 16 + ldrow) * 48 + ldoff);
    uint32_t boff = (uint32_t)(ldrow * 48 + ldoff);
    uint32_t sAh_b = (uint32_t)__cvta_generic_to_shared(sAh);
    uint32_t sAl_b = (uint32_t)__cvta_generic_to_shared(sAl);
    uint32_t sBh_b = (uint32_t)__cvta_generic_to_shared(sBh);
    uint32_t sBl_b = (uint32_t)__cvta_generic_to_shared(sBl);

    float c[4][4];
#pragma unroll
    for (int nt = 0; nt < 4; nt++)
#pragma unroll
        for (int r = 0; r < 4; r++) c[nt][r] = 0.f;

#pragma unroll 1
    for (int kb = 0; kb < D; kb += 16) {
        __syncthreads();
        {
            uint4 hv = *(const uint4*)(g_hh + (size_t)grow * D + kb + lhalf * 8);
            uint4 lv = *(const uint4*)(g_hl + (size_t)grow * D + kb + lhalf * 8);
            *(uint4*)(sAh + lrow * 24 + lhalf * 8) = hv;
            *(uint4*)(sAl + lrow * 24 + lhalf * 8) = lv;
        }
        if (tid < 64) {
            int brow = tid >> 1;
            int bh2  = tid & 1;
            uint4 wh = *(const uint4*)(g_wsh + (size_t)brow * D + kb + bh2 * 8);
            uint4 wl = *(const uint4*)(g_wsl + (size_t)brow * D + kb + bh2 * 8);
            *(uint4*)(sBh + brow * 24 + bh2 * 8) = wh;
            *(uint4*)(sBl + brow * 24 + bh2 * 8) = wl;
        }
        __syncthreads();

        uint32_t ah[4], al[4];
        LDSM4(ah[0], ah[1], ah[2], ah[3], sAh_b + aoff);
        LDSM4(al[0], al[1], al[2], al[3], sAl_b + aoff);

#pragma unroll
        for (int ng = 0; ng < 2; ng++) {
            uint32_t bh[4], bl[4];
            LDSM4(bh[0], bh[1], bh[2], bh[3], sBh_b + boff + ng * 16 * 48);
            LDSM4(bl[0], bl[1], bl[2], bl[3], sBl_b + boff + ng * 16 * 48);
#pragma unroll
            for (int sub = 0; sub < 2; sub++) {
                float* cc = c[ng * 2 + sub];
                MMA16816(cc, ah, bh[sub], bh[sub + 2]);
                MMA16816(cc, ah, bl[sub], bl[sub + 2]);
                MMA16816(cc, al, bh[sub], bh[sub + 2]);
            }
        }
    }

    int g = lane >> 2;
    int q = (lane & 3) * 2;
    int r0 = rowBase + warp * 16 + g;
#pragma unroll
    for (int nt = 0; nt < 4; nt++) {
        int col = nt * 8 + q;
        float* cc = c[nt];
        if (r0 < N_NODES)
            *(float2*)(pq + (size_t)r0 * 32 + col) = make_float2(cc[0], cc[1]);
        if (r0 + 8 < N_NODES)
            *(float2*)(pq + (size_t)(r0 + 8) * 32 + col) = make_float2(cc[2], cc[3]);
    }
}

// ---------------- layer-2 aggregation + final output (16-dim) ---------------
__global__ void k_agg_out(float* __restrict__ out) {
    int t = blockIdx.x * blockDim.x + threadIdx.x;
    int node = t >> 2;
    int sub  = t & 3;
    if (node >= N_NODES) return;
    int deg = min(g_cnt[node], CAP);
    const int* adj = g_csr + (size_t)node * CAP;
    const float4* pq4 = (const float4*)g_pq;
    float4 acc = make_float4(0.f, 0.f, 0.f, 0.f);
    for (int i = 0; i < deg; i++) {
        int s = adj[i];
        float4 v = pq4[(size_t)s * 8 + sub];
        acc.x += v.x; acc.y += v.y; acc.z += v.z; acc.w += v.w;
    }
    float inv = 1.0f / (float)max(deg, 1);
    float4 qv = pq4[(size_t)node * 8 + 4 + sub];
    float4 bv = *(const float4*)(g_bco + sub * 4);
    float4 o;
    o.x = acc.x * inv + qv.x + bv.x;
    o.y = acc.y * inv + qv.y + bv.y;
    o.z = acc.z * inv + qv.z + bv.z;
    o.w = acc.w * inv + qv.w + bv.w;
    ((float4*)out)[(size_t)node * 4 + sub] = o;
}

// ---------------- launch ----------------------------------------------------
extern "C" void kernel_launch(void* const* d_in, const int* in_sizes, int n_in,
                              void* d_out, int out_size)
{
    const float* x   = (const float*)d_in[0];
    const int*   ei  = (const int*)d_in[1];
    const float* W1l = (const float*)d_in[2];
    const float* b1l = (const float*)d_in[3];
    const float* W1r = (const float*)d_in[4];
    const float* W2l = (const float*)d_in[5];
    const float* b2l = (const float*)d_in[6];
    const float* W2r = (const float*)d_in[7];
    const float* Wc  = (const float*)d_in[8];
    const float* bc  = (const float*)d_in[9];
    float* out = (float*)d_out;

    const int* src = ei;
    const int* dst = ei + N_EDGES;

    float* pq;
    cudaGetSymbolAddress((void**)&pq, g_pq);

    // prep (zero cnt + weight prep) + x split + bucket scatter
    k_prep<<<ZERO_BLKS + 32 + 4, 1024>>>(W1l, W1r, Wc, W2l, W2r, b2l, bc);
    k_convx<<<(N_NODES * D / 4 + 255) / 256, 256>>>(x);
    k_scatter<<<2048, 256>>>(src, dst);

    // layer 1
    k_aggregate<<<(N_NODES * 32 + 255) / 256, 256>>>(x);
    k_gemm<<<GEMM_BLOCKS, GT>>>(b1l);

    // layer 2 (composed through classifier)
    k_gemm16<<<GEMM_BLOCKS, GT>>>(pq);
    k_agg_out<<<(N_NODES * 4 + 255) / 256, 256>>>(out);
}

// round 17
// speedup vs baseline: 1.5813x; 1.5813x over previous
#include <cuda_runtime.h>
#include <cuda_bf16.h>
#include <cstdint>

#define N_NODES 100000
#define N_EDGES 1600000
#define D 128
#define DOUT 16
#define CAP 128          // per-node bucket capacity (in-degree ~Poisson(16))

#define BM 128
#define GT 256
#define GEMM_BLOCKS ((N_NODES + BM - 1) / BM)
#define ZERO_BLKS ((N_NODES + 1023) / 1024)   // 98

// ---------------- scratch (static device globals) ---------------------------
__device__ float g_agg[(size_t)N_NODES * D];   // layer-1 aggregation out
__device__ float g_h[(size_t)N_NODES * D];     // hidden activations
__device__ float g_pq[(size_t)N_NODES * 32];   // p (cols 0-15) and q (cols 16-31)
__device__ int   g_cnt[N_NODES];
__device__ int   g_csr[(size_t)N_NODES * CAP]; // bucketed adjacency
__device__ __nv_bfloat16 g_wh[2 * D * D];      // W1l, W1r hi parts
__device__ __nv_bfloat16 g_wl[2 * D * D];      // W1l, W1r lo parts
__device__ __nv_bfloat16 g_wsh[32 * D];        // stacked [Wcl; Wcr] hi
__device__ __nv_bfloat16 g_wsl[32 * D];        // stacked [Wcl; Wcr] lo
__device__ float g_bco[DOUT];                  // Wc@b2l + bc

// ---------------- helpers ---------------------------------------------------
__device__ __forceinline__ uint32_t packbf(float a, float b) {
    uint16_t ha = __bfloat16_as_ushort(__float2bfloat16_rn(a));
    uint16_t hb = __bfloat16_as_ushort(__float2bfloat16_rn(b));
    return (uint32_t)ha | ((uint32_t)hb << 16);
}
__device__ __forceinline__ float residf(float f) {
    return f - __bfloat162float(__float2bfloat16_rn(f));
}

#define LDSM4(r0, r1, r2, r3, addr)                                            \
    asm volatile("ldmatrix.sync.aligned.m8n8.x4.shared.b16 {%0,%1,%2,%3}, [%4];" \
                 : "=r"(r0), "=r"(r1), "=r"(r2), "=r"(r3) : "r"(addr))

#define MMA16816(cc, a, b0, b1)                                                \
    asm volatile("mma.sync.aligned.m16n8k16.row.col.f32.bf16.bf16.f32 "        \
                 "{%0,%1,%2,%3}, {%4,%5,%6,%7}, {%8,%9}, {%0,%1,%2,%3};"       \
                 : "+f"(cc[0]), "+f"(cc[1]), "+f"(cc[2]), "+f"(cc[3])          \
                 : "r"(a[0]), "r"(a[1]), "r"(a[2]), "r"(a[3]), "r"(b0), "r"(b1))

// ---------------- fused prep: zero cnt + weight split + composed weights ----
__global__ void k_prep(const float* __restrict__ W1l, const float* __restrict__ W1r,
                       const float* __restrict__ Wc, const float* __restrict__ W2l,
                       const float* __restrict__ W2r, const float* __restrict__ b2l,
                       const float* __restrict__ bc) {
    int b = blockIdx.x;
    if (b < ZERO_BLKS) {
        int i = b * 1024 + threadIdx.x;
        if (i < N_NODES) g_cnt[i] = 0;
    } else if (b < ZERO_BLKS + 32) {
        int i = (b - ZERO_BLKS) * 1024 + threadIdx.x;
        const float* srcs[2] = {W1l, W1r};
        float v = srcs[i >> 14][i & 16383];
        __nv_bfloat16 h = __float2bfloat16_rn(v);
        g_wh[i] = h;
        g_wl[i] = __float2bfloat16_rn(v - __bfloat162float(h));
    } else {
        int idx = (b - ZERO_BLKS - 32) * 1024 + threadIdx.x;
        int which = idx >> 11;
        int o = (idx >> 7) & 15;
        int k = idx & 127;
        const float* W2 = which ? W2r : W2l;
        float s = 0.f;
#pragma unroll 8
        for (int j = 0; j < D; j++)
            s += Wc[o * D + j] * W2[j * D + k];
        int row = which * 16 + o;
        __nv_bfloat16 hi = __float2bfloat16_rn(s);
        g_wsh[row * D + k] = hi;
        g_wsl[row * D + k] = __float2bfloat16_rn(s - __bfloat162float(hi));
        if (which == 0 && k == 0) {
            float bb = bc[o];
            for (int j = 0; j < D; j++) bb += Wc[o * D + j] * b2l[j];
            g_bco[o] = bb;
        }
    }
}

// ---------------- bucket scatter (replaces hist+scan+scatter) ---------------
__global__ void k_scatter(const int* __restrict__ src, const int* __restrict__ dst) {
    for (int e = blockIdx.x * blockDim.x + threadIdx.x; e < N_EDGES;
         e += gridDim.x * blockDim.x) {
        int d = dst[e];
        int p = atomicAdd(&g_cnt[d], 1);
        if (p < CAP) g_csr[(size_t)d * CAP + p] = src[e];
    }
}

// ---------------- mean aggregation: warp per node, 4-way gather ILP ---------
__global__ void k_aggregate(const float* __restrict__ feat, float* __restrict__ out) {
    int warp = (blockIdx.x * blockDim.x + threadIdx.x) >> 5;
    uint32_t lane = threadIdx.x & 31;
    if (warp >= N_NODES) return;
    int deg = min(g_cnt[warp], CAP);
    const int* adj = g_csr + (size_t)warp * CAP;   // 512B-aligned bucket base
    const float4* f4 = (const float4*)feat;
    float4 acc = make_float4(0.f, 0.f, 0.f, 0.f);
    int i = 0;
    for (; i + 3 < deg; i += 4) {
        int4 s4 = *(const int4*)(adj + i);         // aligned: i % 4 == 0
        uint32_t o0 = (uint32_t)s4.x * 32u + lane;
        uint32_t o1 = (uint32_t)s4.y * 32u + lane;
        uint32_t o2 = (uint32_t)s4.z * 32u + lane;
        uint32_t o3 = (uint32_t)s4.w * 32u + lane;
        float4 v0 = f4[o0];
        float4 v1 = f4[o1];
        float4 v2 = f4[o2];
        float4 v3 = f4[o3];
        acc.x += (v0.x + v1.x) + (v2.x + v3.x);
        acc.y += (v0.y + v1.y) + (v2.y + v3.y);
        acc.z += (v0.z + v1.z) + (v2.z + v3.z);
        acc.w += (v0.w + v1.w) + (v2.w + v3.w);
    }
    for (; i < deg; i++) {
        uint32_t o = (uint32_t)adj[i] * 32u + lane;
        float4 v = f4[o];
        acc.x += v.x; acc.y += v.y; acc.z += v.z; acc.w += v.w;
    }
    float inv = 1.0f / (float)max(deg, 1);
    acc.x *= inv; acc.y *= inv; acc.z *= inv; acc.w *= inv;
    ((float4*)out)[(uint32_t)warp * 32u + lane] = acc;
}

// ---------------- tensor-core dual GEMM (layer 1, N=128) --------------------
__global__ __launch_bounds__(GT, 2)
void k_gemm(const float* __restrict__ A1, const float* __restrict__ A2,
            const float* __restrict__ bias, float* __restrict__ out)
{
    __shared__ __align__(16) __nv_bfloat16 sAh[BM * 24];
    __shared__ __align__(16) __nv_bfloat16 sAl[BM * 24];
    __shared__ __align__(16) __nv_bfloat16 sBh[BM * 24];
    __shared__ __align__(16) __nv_bfloat16 sBl[BM * 24];
    __shared__ float sbias[D];

    int tid  = threadIdx.x;
    int lane = tid & 31;
    int warp = tid >> 5;
    int warp_m = warp & 3;
    int warp_n = warp >> 2;
    int rowBase = blockIdx.x * BM;

    if (tid < D) sbias[tid] = bias[tid];

    int lrow  = tid >> 1;
    int lhalf = tid & 1;

    int ldrow = lane & 15;
    int ldoff = (lane >> 4) * 16;
    uint32_t aoff = (uint32_t)((warp_m * 32 + ldrow) * 48 + ldoff);
    uint32_t boff = (uint32_t)((warp_n * 64 + ldrow) * 48 + ldoff);
    uint32_t sAh_b = (uint32_t)__cvta_generic_to_shared(sAh);
    uint32_t sAl_b = (uint32_t)__cvta_generic_to_shared(sAl);
    uint32_t sBh_b = (uint32_t)__cvta_generic_to_shared(sBh);
    uint32_t sBl_b = (uint32_t)__cvta_generic_to_shared(sBl);

    float c[2][8][4];
#pragma unroll
    for (int mt = 0; mt < 2; mt++)
#pragma unroll
        for (int nc = 0; nc < 8; nc++)
#pragma unroll
            for (int r = 0; r < 4; r++) c[mt][nc][r] = 0.f;

    int grow = rowBase + lrow;
    bool rowOk = grow < N_NODES;

#pragma unroll 1
    for (int ph = 0; ph < 2; ph++) {
        const float* A = ph ? A2 : A1;
        const __nv_bfloat16* Wh = g_wh + (size_t)ph * D * D;
        const __nv_bfloat16* Wl = g_wl + (size_t)ph * D * D;

#pragma unroll 1
        for (int kb = 0; kb < D; kb += 16) {
            __syncthreads();
            float v0 = 0.f, v1 = 0.f, v2 = 0.f, v3 = 0.f;
            float v4 = 0.f, v5 = 0.f, v6 = 0.f, v7 = 0.f;
            if (rowOk) {
                const float* ap = A + (size_t)grow * D + kb + lhalf * 8;
                float4 f0 = *(const float4*)ap;
                float4 f1 = *(const float4*)(ap + 4);
                v0 = f0.x; v1 = f0.y; v2 = f0.z; v3 = f0.w;
                v4 = f1.x; v5 = f1.y; v6 = f1.z; v7 = f1.w;
            }
            {
                uint4 h = make_uint4(packbf(v0, v1), packbf(v2, v3),
                                     packbf(v4, v5), packbf(v6, v7));
                uint4 l = make_uint4(packbf(residf(v0), residf(v1)),
                                     packbf(residf(v2), residf(v3)),
                                     packbf(residf(v4), residf(v5)),
                                     packbf(residf(v6), residf(v7)));
                *(uint4*)(sAh + lrow * 24 + lhalf * 8) = h;
                *(uint4*)(sAl + lrow * 24 + lhalf * 8) = l;
            }
            {
                uint4 wh = *(const uint4*)(Wh + (size_t)lrow * D + kb + lhalf * 8);
                uint4 wl = *(const uint4*)(Wl + (size_t)lrow * D + kb + lhalf * 8);
                *(uint4*)(sBh + lrow * 24 + lhalf * 8) = wh;
                *(uint4*)(sBl + lrow * 24 + lhalf * 8) = wl;
            }
            __syncthreads();

            uint32_t ah[2][4], al[2][4];
            LDSM4(ah[0][0], ah[0][1], ah[0][2], ah[0][3], sAh_b + aoff);
            LDSM4(ah[1][0], ah[1][1], ah[1][2], ah[1][3], sAh_b + aoff + 16 * 48);
            LDSM4(al[0][0], al[0][1], al[0][2], al[0][3], sAl_b + aoff);
            LDSM4(al[1][0], al[1][1], al[1][2], al[1][3], sAl_b + aoff + 16 * 48);

#pragma unroll
            for (int ng = 0; ng < 4; ng++) {
                uint32_t bh[4], bl[4];
                LDSM4(bh[0], bh[1], bh[2], bh[3], sBh_b + boff + ng * 16 * 48);
                LDSM4(bl[0], bl[1], bl[2], bl[3], sBl_b + boff + ng * 16 * 48);
#pragma unroll
                for (int mt = 0; mt < 2; mt++) {
#pragma unroll
                    for (int sub = 0; sub < 2; sub++) {
                        float* cc = c[mt][ng * 2 + sub];
                        MMA16816(cc, ah[mt], bh[sub], bh[sub + 2]);
                        MMA16816(cc, ah[mt], bl[sub], bl[sub + 2]);
                        MMA16816(cc, al[mt], bh[sub], bh[sub + 2]);
                    }
                }
            }
        }
    }
    __syncthreads();

    int g = lane >> 2;
    int q = (lane & 3) * 2;
#pragma unroll
    for (int mt = 0; mt < 2; mt++) {
        int r0 = rowBase + warp_m * 32 + mt * 16 + g;
#pragma unroll
        for (int nc = 0; nc < 8; nc++) {
            int col = warp_n * 64 + nc * 8 + q;
            float b0 = sbias[col], b1 = sbias[col + 1];
            float* cc = c[mt][nc];
            float o0 = fmaxf(cc[0] + b0, 0.f);
            float o1 = fmaxf(cc[1] + b1, 0.f);
            float o2 = fmaxf(cc[2] + b0, 0.f);
            float o3 = fmaxf(cc[3] + b1, 0.f);
            if (r0 < N_NODES)
                *(float2*)(out + (size_t)r0 * D + col) = make_float2(o0, o1);
            if (r0 + 8 < N_NODES)
                *(float2*)(out + (size_t)(r0 + 8) * D + col) = make_float2(o2, o3);
        }
    }
}

// ---------------- layer-2 composed GEMM: pq = h @ [Wcl;Wcr]^T (N=32) --------
__global__ __launch_bounds__(GT, 2)
void k_gemm16(const float* __restrict__ A, float* __restrict__ pq)
{
    __shared__ __align__(16) __nv_bfloat16 sAh[BM * 24];
    __shared__ __align__(16) __nv_bfloat16 sAl[BM * 24];
    __shared__ __align__(16) __nv_bfloat16 sBh[32 * 24];
    __shared__ __align__(16) __nv_bfloat16 sBl[32 * 24];

    int tid  = threadIdx.x;
    int lane = tid & 31;
    int warp = tid >> 5;
    int rowBase = blockIdx.x * BM;

    int lrow  = tid >> 1;
    int lhalf = tid & 1;

    int ldrow = lane & 15;
    int ldoff = (lane >> 4) * 16;
    uint32_t aoff = (uint32_t)((warp * 16 + ldrow) * 48 + ldoff);
    uint32_t boff = (uint32_t)(ldrow * 48 + ldoff);
    uint32_t sAh_b = (uint32_t)__cvta_generic_to_shared(sAh);
    uint32_t sAl_b = (uint32_t)__cvta_generic_to_shared(sAl);
    uint32_t sBh_b = (uint32_t)__cvta_generic_to_shared(sBh);
    uint32_t sBl_b = (uint32_t)__cvta_generic_to_shared(sBl);

    float c[4][4];
#pragma unroll
    for (int nt = 0; nt < 4; nt++)
#pragma unroll
        for (int r = 0; r < 4; r++) c[nt][r] = 0.f;

    int grow = rowBase + lrow;
    bool rowOk = grow < N_NODES;

#pragma unroll 1
    for (int kb = 0; kb < D; kb += 16) {
        __syncthreads();
        float v0 = 0.f, v1 = 0.f, v2 = 0.f, v3 = 0.f;
        float v4 = 0.f, v5 = 0.f, v6 = 0.f, v7 = 0.f;
        if (rowOk) {
            const float* ap = A + (size_t)grow * D + kb + lhalf * 8;
            float4 f0 = *(const float4*)ap;
            float4 f1 = *(const float4*)(ap + 4);
            v0 = f0.x; v1 = f0.y; v2 = f0.z; v3 = f0.w;
            v4 = f1.x; v5 = f1.y; v6 = f1.z; v7 = f1.w;
        }
        {
            uint4 h = make_uint4(packbf(v0, v1), packbf(v2, v3),
                                 packbf(v4, v5), packbf(v6, v7));
            uint4 l = make_uint4(packbf(residf(v0), residf(v1)),
                                 packbf(residf(v2), residf(v3)),
                                 packbf(residf(v4), residf(v5)),
                                 packbf(residf(v6), residf(v7)));
            *(uint4*)(sAh + lrow * 24 + lhalf * 8) = h;
            *(uint4*)(sAl + lrow * 24 + lhalf * 8) = l;
        }
        if (tid < 64) {
            int brow = tid >> 1;
            int bh2  = tid & 1;
            uint4 wh = *(const uint4*)(g_wsh + (size_t)brow * D + kb + bh2 * 8);
            uint4 wl = *(const uint4*)(g_wsl + (size_t)brow * D + kb + bh2 * 8);
            *(uint4*)(sBh + brow * 24 + bh2 * 8) = wh;
            *(uint4*)(sBl + brow * 24 + bh2 * 8) = wl;
        }
        __syncthreads();

        uint32_t ah[4], al[4];
        LDSM4(ah[0], ah[1], ah[2], ah[3], sAh_b + aoff);
        LDSM4(al[0], al[1], al[2], al[3], sAl_b + aoff);

#pragma unroll
        for (int ng = 0; ng < 2; ng++) {
            uint32_t bh[4], bl[4];
            LDSM4(bh[0], bh[1], bh[2], bh[3], sBh_b + boff + ng * 16 * 48);
            LDSM4(bl[0], bl[1], bl[2], bl[3], sBl_b + boff + ng * 16 * 48);
#pragma unroll
            for (int sub = 0; sub < 2; sub++) {
                float* cc = c[ng * 2 + sub];
                MMA16816(cc, ah, bh[sub], bh[sub + 2]);
                MMA16816(cc, ah, bl[sub], bl[sub + 2]);
                MMA16816(cc, al, bh[sub], bh[sub + 2]);
            }
        }
    }

    int g = lane >> 2;
    int q = (lane & 3) * 2;
    int r0 = rowBase + warp * 16 + g;
#pragma unroll
    for (int nt = 0; nt < 4; nt++) {
        int col = nt * 8 + q;
        float* cc = c[nt];
        if (r0 < N_NODES)
            *(float2*)(pq + (size_t)r0 * 32 + col) = make_float2(cc[0], cc[1]);
        if (r0 + 8 < N_NODES)
            *(float2*)(pq + (size_t)(r0 + 8) * 32 + col) = make_float2(cc[2], cc[3]);
    }
}

// ---------------- layer-2 aggregation + final output (16-dim) ---------------
__global__ void k_agg_out(float* __restrict__ out) {
    int t = blockIdx.x * blockDim.x + threadIdx.x;
    int node = t >> 2;
    uint32_t sub = t & 3;
    if (node >= N_NODES) return;
    int deg = min(g_cnt[node], CAP);
    const int* adj = g_csr + (size_t)node * CAP;
    const float4* pq4 = (const float4*)g_pq;
    float4 acc = make_float4(0.f, 0.f, 0.f, 0.f);
    int i = 0;
    for (; i + 3 < deg; i += 4) {
        int4 s4 = *(const int4*)(adj + i);
        float4 v0 = pq4[(uint32_t)s4.x * 8u + sub];
        float4 v1 = pq4[(uint32_t)s4.y * 8u + sub];
        float4 v2 = pq4[(uint32_t)s4.z * 8u + sub];
        float4 v3 = pq4[(uint32_t)s4.w * 8u + sub];
        acc.x += (v0.x + v1.x) + (v2.x + v3.x);
        acc.y += (v0.y + v1.y) + (v2.y + v3.y);
        acc.z += (v0.z + v1.z) + (v2.z + v3.z);
        acc.w += (v0.w + v1.w) + (v2.w + v3.w);
    }
    for (; i < deg; i++) {
        float4 v = pq4[(uint32_t)adj[i] * 8u + sub];
        acc.x += v.x; acc.y += v.y; acc.z += v.z; acc.w += v.w;
    }
    float inv = 1.0f / (float)max(deg, 1);
    float4 qv = pq4[(uint32_t)node * 8u + 4u + sub];
    float4 bv = *(const float4*)(g_bco + sub * 4);
    float4 o;
    o.x = acc.x * inv + qv.x + bv.x;
    o.y = acc.y * inv + qv.y + bv.y;
    o.z = acc.z * inv + qv.z + bv.z;
    o.w = acc.w * inv + qv.w + bv.w;
    ((float4*)out)[(uint32_t)node * 4u + sub] = o;
}

// ---------------- launch ----------------------------------------------------
extern "C" void kernel_launch(void* const* d_in, const int* in_sizes, int n_in,
                              void* d_out, int out_size)
{
    const float* x   = (const float*)d_in[0];
    const int*   ei  = (const int*)d_in[1];
    const float* W1l = (const float*)d_in[2];
    const float* b1l = (const float*)d_in[3];
    const float* W1r = (const float*)d_in[4];
    const float* W2l = (const float*)d_in[5];
    const float* b2l = (const float*)d_in[6];
    const float* W2r = (const float*)d_in[7];
    const float* Wc  = (const float*)d_in[8];
    const float* bc  = (const float*)d_in[9];
    float* out = (float*)d_out;

    const int* src = ei;
    const int* dst = ei + N_EDGES;

    float *agg, *h, *pq;
    cudaGetSymbolAddress((void**)&agg, g_agg);
    cudaGetSymbolAddress((void**)&h, g_h);
    cudaGetSymbolAddress((void**)&pq, g_pq);

    // prep (zero cnt + weight prep), then direct bucket scatter
    k_prep<<<ZERO_BLKS + 32 + 4, 1024>>>(W1l, W1r, Wc, W2l, W2r, b2l, bc);
    k_scatter<<<2048, 256>>>(src, dst);

    // layer 1
    k_aggregate<<<(N_NODES * 32 + 255) / 256, 256>>>(x, agg);
    k_gemm<<<GEMM_BLOCKS, GT>>>(agg, x, b1l, h);

    // layer 2 (composed through classifier)
    k_gemm16<<<GEMM_BLOCKS, GT>>>(h, pq);
    k_agg_out<<<(N_NODES * 4 + 255) / 256, 256>>>(out);
}